// round 15
// baseline (speedup 1.0000x reference)
#include <cuda_runtime.h>
#include <math.h>

#define Bn    128
#define Tn    128
#define In    512
#define Hn    512
#define Dn    1024
#define Nn    513
#define NP    576
#define DEPTH 4
#define EPSV  1e-5f
#define NCTA  296         // 2 CTAs per SM
#define NTHR  256
#define NG    4           // independent groups
#define GCTA  74          // CTAs per group
#define GB    32          // batches per group
#define KS    8           // split-K in scan (chunks of 128)

typedef unsigned long long u64t;

// ----------------------------- device state --------------------------------
__device__ float g_Wp[Dn * NP];
__device__ float g_Up[Dn * NP];
__device__ float g_X[Tn * Bn * Dn];       // xs / h_seq in place, row = t*Bn+b
__device__ float g_XWraw[Tn * Bn * NP];
__device__ float g_spre[Tn * Bn * NP];
__device__ float g_Gpart[Bn * KS * NP];   // [b][ks][NP]
__device__ float g_h[Bn * Dn];
__device__ float g_fkseq[Tn * Bn];
__device__ float g_hvseq[Tn * Bn];
__device__ unsigned g_ctrM[NG * 64];      // monotonic counters, 256B apart
__device__ unsigned g_pCnt, g_pEp;        // global prep barrier

// --------------------------- f32x2 packed math ------------------------------
__device__ __forceinline__ void ffma2(u64t& d, u64t a, u64t b) {
    asm("fma.rn.f32x2 %0, %1, %2, %0;" : "+l"(d) : "l"(a), "l"(b));
}
__device__ __forceinline__ u64t packdup(float x) {
    u64t r; asm("mov.b64 %0, {%1, %1};" : "=l"(r) : "f"(x)); return r;
}
__device__ __forceinline__ float2 unpack2(u64t v) {
    float2 f; asm("mov.b64 {%0, %1}, %2;" : "=f"(f.x), "=f"(f.y) : "l"(v)); return f;
}

// ------------------------------ barriers ------------------------------------
__device__ __forceinline__ unsigned ld_acq(unsigned* p) {
    unsigned v;
    asm volatile("ld.acquire.gpu.u32 %0, [%1];" : "=r"(v) : "l"(p) : "memory");
    return v;
}
__device__ __forceinline__ void prep_barrier(unsigned& ep) {
    __syncthreads();
    if (threadIdx.x == 0) {
        ep += 1;
        __threadfence();
        unsigned prev = atomicAdd(&g_pCnt, 1u);
        if (prev == (unsigned)(NCTA - 1)) {
            atomicExch(&g_pCnt, 0u);
            __threadfence();
            atomicExch(&g_pEp, ep);
        } else {
            while (ld_acq(&g_pEp) < ep) { }
        }
        __threadfence();
    }
    __syncthreads();
}
__device__ __forceinline__ void bar_arrive(int g, unsigned& k) {
    __syncthreads();
    if (threadIdx.x == 0) {
        k += (unsigned)GCTA;
        __threadfence();
        asm volatile("red.release.gpu.add.u32 [%0], 1;" :: "l"(&g_ctrM[g * 64]) : "memory");
    }
}
__device__ __forceinline__ void bar_wait(int g, unsigned base, unsigned k) {
    if (threadIdx.x == 0) {
        while ((unsigned)(ld_acq(&g_ctrM[g * 64]) - base) < k) { }
        __threadfence();
    }
    __syncthreads();
}

// ------------------- staging helpers (256 threads) --------------------------
// A chunk: 32 rows x 64 k from A (lda), transposed into hT[k][row] (stride 36)
__device__ __forceinline__ void stage_AT(float* hT, const float* A, int lda, int k0) {
    int tid = threadIdx.x;
    int row = tid & 31;
    int kh  = (tid >> 5) << 3;     // 0..56 step 8
    const float* src = A + (size_t)row * lda + k0 + kh;
    float4 v0 = *(const float4*)src;
    float4 v1 = *(const float4*)(src + 4);
    hT[(kh + 0) * 36 + row] = v0.x;
    hT[(kh + 1) * 36 + row] = v0.y;
    hT[(kh + 2) * 36 + row] = v0.z;
    hT[(kh + 3) * 36 + row] = v0.w;
    hT[(kh + 4) * 36 + row] = v1.x;
    hT[(kh + 5) * 36 + row] = v1.y;
    hT[(kh + 6) * 36 + row] = v1.z;
    hT[(kh + 7) * 36 + row] = v1.w;
}
// B chunk: 64 k x 64 cols (row stride NP) -> Uc[k*64 + c]
__device__ __forceinline__ void stage_Bc(float* Uc, const float* Bg, int k0, int n0) {
    int tid = threadIdx.x;
    int kr = tid >> 2;
    int cq = (tid & 3) << 4;
    const float* src = Bg + (size_t)(k0 + kr) * NP + n0 + cq;
#pragma unroll
    for (int q = 0; q < 4; q++)
        *(float4*)&Uc[(kr << 6) + cq + (q << 2)] = *(const float4*)(src + (q << 2));
}
// 32x64 GEMM over one 64-K chunk; 256 threads, 2m x 4n microtile
__device__ __forceinline__ void gemm64(u64t acc[2][2], const float* hT,
                                       const float* Uc, int ty, int tx) {
#pragma unroll 16
    for (int kk = 0; kk < 64; kk++) {
        float2 a = *(const float2*)(hT + kk * 36 + (ty << 1));
        const u64t* up = (const u64t*)(Uc + (kk << 6) + (tx << 2));
        u64t b0 = up[0], b1 = up[1];
        u64t ad;
        ad = packdup(a.x); ffma2(acc[0][0], ad, b0); ffma2(acc[0][1], ad, b1);
        ad = packdup(a.y); ffma2(acc[1][0], ad, b0); ffma2(acc[1][1], ad, b1);
    }
}

// ------------------------------ main kernel ---------------------------------
__global__ void __launch_bounds__(NTHR, 2) hrnn_kernel(
    const float* __restrict__ x, const int* __restrict__ mask,
    const float* __restrict__ W, const float* __restrict__ U,
    const float* __restrict__ bias, const float* __restrict__ gam,
    const float* __restrict__ bet, float* __restrict__ out)
{
    __shared__ __align__(16) float sh_Uc[64 * 64];   // 16 KB
    __shared__ __align__(16) float sh_hT[64 * 36];   // 9.2 KB
    __shared__ float sh_s[Nn];
    __shared__ float sh_red[16];
    __shared__ float sh_sc[8];

    int cta = blockIdx.x, tid = threadIdx.x;
    int gtid = cta * NTHR + tid;
    const int nthr = NCTA * NTHR;

    // ------------------------------- prep -----------------------------------
    for (int i = gtid; i < Tn * Bn * Dn; i += nthr) {
        int d = i & (Dn - 1);
        int row = i >> 10;
        int t = row >> 7, b = row & 127;
        g_X[i] = (d < In) ? x[(b * Tn + t) * In + d] : 0.f;
    }
    for (int i = gtid; i < Dn * NP; i += nthr) {
        int col = i % NP, r = i / NP;
        float wv = 0.f, uv = 0.f;
        if (col < Nn) { wv = W[r * Nn + col]; uv = U[r * Nn + col]; }
        g_Wp[i] = wv;
        g_Up[i] = uv;
    }
    for (int i = gtid; i < Tn * Bn; i += nthr) { g_fkseq[i] = 0.f; g_hvseq[i] = 1.f; }

    int g = cta / GCTA;       // SM s hosts cta s and s+148 -> groups {0,2} or {1,3}
    int c = cta - g * GCTA;
    const int b0 = g * GB;

    unsigned base = 0, kbar = 0, epP = 0;
    if (tid == 0) {
        base = ld_acq(&g_ctrM[g * 64]);   // sample before any arrival this launch
        epP  = ld_acq(&g_pEp);
    }
    prep_barrier(epP);

    const float* gam0 = gam;
    const float* gam1 = gam + Nn;
    const float* bet0 = bet;
    const float* bet1 = bet + Nn;
    float g1a = gam1[tid], b1a = bet1[tid];
    float g1b = gam1[tid + 256], b1b = bet1[tid + 256];
    float g1z = gam1[512], b1z = bet1[512];
    float g1_0 = gam1[0], b1_0 = bet1[0];
    float bias0 = bias[0];

    int ks = c / 9, j = c - ks * 9;       // scan role (c < 72)
    int ty = tid >> 4, tx = tid & 15;     // gemm microtile role
    u64t acc[2][2];

    for (int lev = 0; lev < DEPTH; lev++) {
        // -------- xW GEMM: group's 1152 tiles of 32x64, K=1024 ---------------
        for (int tau = c; tau < Tn * 9; tau += GCTA) {
            int t = tau / 9, j2 = tau - t * 9;
            acc[0][0] = 0ull; acc[0][1] = 0ull; acc[1][0] = 0ull; acc[1][1] = 0ull;
            const float* Abase = &g_X[(size_t)(t * Bn + b0) * Dn];
            for (int ch = 0; ch < 16; ch++) {
                __syncthreads();
                stage_AT(sh_hT, Abase, Dn, ch * 64);
                stage_Bc(sh_Uc, g_Wp, ch * 64, j2 * 64);
                __syncthreads();
                gemm64(acc, sh_hT, sh_Uc, ty, tx);
            }
#pragma unroll
            for (int i = 0; i < 2; i++) {
                float2 p0 = unpack2(acc[i][0]), p1 = unpack2(acc[i][1]);
                *(float4*)&g_XWraw[(size_t)(t * Bn + b0 + (ty << 1) + i) * NP
                                   + j2 * 64 + (tx << 2)] =
                    make_float4(p0.x, p0.y, p1.x, p1.y);
            }
        }
        bar_arrive(g, kbar); bar_wait(g, base, kbar);

        // -------- LN of group's xW rows -> spre; zero group's h --------------
        for (int lr = c; lr < Tn * GB; lr += GCTA) {
            int t = lr >> 5, bl = lr & 31;
            const float* row = &g_XWraw[(size_t)(t * Bn + b0 + bl) * NP];
            float v0 = row[tid];
            float v1 = row[tid + 256];
            float v2 = (tid == 0) ? row[512] : 0.f;
            float s = v0 + v1 + v2;
            float q = v0 * v0 + v1 * v1 + v2 * v2;
#pragma unroll
            for (int o = 16; o > 0; o >>= 1) {
                s += __shfl_down_sync(0xffffffffu, s, o);
                q += __shfl_down_sync(0xffffffffu, q, o);
            }
            if ((tid & 31) == 0) { sh_red[tid >> 5] = s; sh_red[8 + (tid >> 5)] = q; }
            __syncthreads();
            if (tid == 0) {
                float S = 0.f, Q = 0.f;
#pragma unroll
                for (int w = 0; w < 8; w++) { S += sh_red[w]; Q += sh_red[8 + w]; }
                float mean = S * (1.f / (float)Nn);
                float var  = Q * (1.f / (float)Nn) - mean * mean;
                sh_sc[0] = mean;
                sh_sc[1] = 1.f / (sqrtf(var + EPSV) + EPSV);
            }
            __syncthreads();
            float mean = sh_sc[0], inv = sh_sc[1];
            float* o = &g_spre[(size_t)(t * Bn + b0 + bl) * NP];
            o[tid]       = gam0[tid] * ((v0 - mean) * inv) + bet0[tid] + bias[tid];
            o[tid + 256] = gam0[tid + 256] * ((v1 - mean) * inv) + bet0[tid + 256] + bias[tid + 256];
            if (tid == 0)
                o[512] = gam0[512] * ((v2 - mean) * inv) + bet0[512] + bias[512];
            __syncthreads();
        }
        for (int i = c * NTHR + tid; i < GB * Dn; i += GCTA * NTHR)
            g_h[(size_t)b0 * Dn + i] = 0.f;
        bar_arrive(g, kbar); bar_wait(g, base, kbar);

        // ------------------------------ scan ---------------------------------
        float fk_c = 0.f, hv_c = 0.f;
        int prevmk = 0;
        float spv0 = 0.f, spv1 = 0.f, spv2 = 0.f;
        float xt[4], ht[4];
        float fkpt = 0.f, fkpv = 0.f, hvpv = 0.f;
        int mval = 0;

        for (int t = 0; t < Tn; t++) {
            // ---- phase A: h@U partial tile 32x64, K=128 (2 chunks) ----------
            if (c < KS * 9) {
                acc[0][0] = 0ull; acc[0][1] = 0ull; acc[1][0] = 0ull; acc[1][1] = 0ull;
                for (int ch = 0; ch < 2; ch++) {
                    __syncthreads();
                    stage_AT(sh_hT, &g_h[(size_t)b0 * Dn], Dn, ks * 128 + ch * 64);
                    stage_Bc(sh_Uc, g_Up, ks * 128 + ch * 64, j * 64);
                    __syncthreads();
                    gemm64(acc, sh_hT, sh_Uc, ty, tx);
                }
#pragma unroll
                for (int i = 0; i < 2; i++) {
                    float2 p0 = unpack2(acc[i][0]), p1 = unpack2(acc[i][1]);
                    *(float4*)&g_Gpart[(size_t)((b0 + (ty << 1) + i) * KS + ks) * NP
                                       + j * 64 + (tx << 2)] =
                        make_float4(p0.x, p0.y, p1.x, p1.y);
                }
            }
            bar_arrive(g, kbar);
            // prefetch phase-B operands (all barrier-independent)
            if (c < GB) {
                int b = b0 + c;
                const float* sp = &g_spre[(size_t)(t * Bn + b) * NP];
                spv0 = sp[tid];
                spv1 = sp[tid + 256];
#pragma unroll
                for (int e = 0; e < 4; e++) {
                    xt[e] = g_X[(size_t)(t * Bn + b) * Dn + tid + (e << 8)];
                    ht[e] = g_h[(size_t)b * Dn + tid + (e << 8)];
                }
                if (tid == 0) {
                    spv2 = sp[512];
                    mval = mask[b * Tn + t];
                    fkpt = g_fkseq[t * Bn + b];
                    fkpv = (t + 1 < Tn) ? g_fkseq[(t + 1) * Bn + b] : 0.f;
                    hvpv = g_hvseq[t * Bn + b];
                }
            }
            bar_wait(g, base, kbar);

            // ---- phase B: one CTA per batch ---------------------------------
            if (c < GB) {
                int b = b0 + c;
                const float* gp = &g_Gpart[(size_t)b * KS * NP];
                float v0 = 0.f, v1 = 0.f, v2 = 0.f;
#pragma unroll
                for (int kq = 0; kq < KS; kq++) {
                    v0 += gp[kq * NP + tid];
                    v1 += gp[kq * NP + 256 + tid];
                    if (tid == 0) v2 += gp[kq * NP + 512];
                }
                float s = v0 + v1 + v2;
                float q = v0 * v0 + v1 * v1 + v2 * v2;
#pragma unroll
                for (int o = 16; o > 0; o >>= 1) {
                    s += __shfl_down_sync(0xffffffffu, s, o);
                    q += __shfl_down_sync(0xffffffffu, q, o);
                }
                if ((tid & 31) == 0) { sh_red[tid >> 5] = s; sh_red[8 + (tid >> 5)] = q; }
                __syncthreads();
                if (tid == 0) {
                    float S = 0.f, Q = 0.f;
#pragma unroll
                    for (int w = 0; w < 8; w++) { S += sh_red[w]; Q += sh_red[8 + w]; }
                    float mean = S * (1.f / (float)Nn);
                    float var  = Q * (1.f / (float)Nn) - mean * mean;
                    sh_sc[0] = mean;
                    sh_sc[1] = 1.f / (sqrtf(var + EPSV) + EPSV);
                }
                __syncthreads();
                float mean = sh_sc[0], inv = sh_sc[1];

                float s0 = spv0 + g1a * ((v0 - mean) * inv) + b1a;
                float s1 = spv1 + g1b * ((v1 - mean) * inv) + b1b;
                sh_s[tid]       = s0;
                sh_s[tid + 256] = s1;
                if (tid == 0)
                    sh_s[512] = spv2 + g1z * ((v2 - mean) * inv) + b1z;

                if (tid == 0) {
                    float sum2_0 = g1_0 * ((v0 - mean) * inv) + b1_0;
                    bool mk  = mval > 0;
                    bool mk2 = (t > 0) && (prevmk > 0) && !mk;

                    float fk_both = fminf(fmaxf(0.2f * s0 + 0.5f, 0.f), 1.f);
                    float fk_t1   = fminf(fmaxf(0.2f * (sum2_0 + bias0) + 0.5f, 0.f), 1.f);
                    float fk = fkpt + (1.f - fkpt) *
                               (fk_c * fk_both + (1.f - fk_c) * fk_t1);
                    if (mk2) fk = 0.f;

                    float h_only = hv_c * fk * (fkpv + (1.f - fkpv) * (1.f - hvpv));
                    float x_only = hvpv * (1.f - fkpv) * (1.f - fk + fk * (1.f - hv_c));
                    float both   = (1.f - fkpv) * fk * hv_c * hvpv;
                    float hv = 1.f - (1.f - h_only) * (1.f - x_only) * (1.f - both);

                    float fk_out = mk ? fk : fk_c;
                    float hv_out = mk ? hv : hv_c;
                    if (mk2) fk_out = 0.f;

                    sh_sc[2] = h_only; sh_sc[3] = x_only;
                    sh_sc[4] = both;   sh_sc[5] = mk ? 1.f : 0.f;

                    g_fkseq[t * Bn + b] = fk_out;
                    g_hvseq[t * Bn + b] = hv_out;
                    fk_c = fk_out; hv_c = hv_out; prevmk = mval;
                }
                __syncthreads();

                float h_only = sh_sc[2], x_only = sh_sc[3];
                float both = sh_sc[4], mkf = sh_sc[5];
#pragma unroll
                for (int e = 0; e < 4; e++) {
                    int d = tid + (e << 8);
                    float h_new = (d < In) ? 0.f : tanhf(sh_s[d - (In - 1)]);
                    float h = h_only * ht[e] + x_only * xt[e] + both * h_new;
                    h = mkf * h + (1.f - mkf) * ht[e];
                    g_h[(size_t)b * Dn + d] = h;
                    g_X[(size_t)(t * Bn + b) * Dn + d] = h;
                }
            }
            bar_arrive(g, kbar); bar_wait(g, base, kbar);
        }
    }

    // ------------------------------ output ----------------------------------
    for (int i = c * NTHR + tid; i < GB * Hn; i += GCTA * NTHR) {
        int bl = i >> 9, jj = i & 511;
        out[(size_t)(b0 + bl) * Hn + jj] = g_h[(size_t)(b0 + bl) * Dn + In + jj];
    }
}

// ------------------------------- launcher -----------------------------------
extern "C" void kernel_launch(void* const* d_in, const int* in_sizes, int n_in,
                              void* d_out, int out_size) {
    const float* x      = (const float*)d_in[0];
    const int*   mask   = (const int*)d_in[1];
    const float* W      = (const float*)d_in[2];
    const float* U      = (const float*)d_in[3];
    const float* bias   = (const float*)d_in[4];
    const float* gammas = (const float*)d_in[5];
    const float* betas  = (const float*)d_in[6];
    float* out = (float*)d_out;

    hrnn_kernel<<<NCTA, NTHR>>>(x, mask, W, U, bias, gammas, betas, out);
}

// round 16
// speedup vs baseline: 1.0169x; 1.0169x over previous
#include <cuda_runtime.h>
#include <math.h>

#define Bn    128
#define Tn    128
#define In    512
#define Hn    512
#define Dn    1024
#define Nn    513
#define NP    576
#define DEPTH 4
#define EPSV  1e-5f
#define NCTA  296         // 2 CTAs per SM
#define NTHR  256
#define NG    4           // independent groups
#define GCTA  74          // CTAs per group
#define GB    32          // batches per group
#define KS    8           // split-K in scan (chunks of 128)

typedef unsigned long long u64t;

// ----------------------------- device state --------------------------------
__device__ float g_Wp[Dn * NP];
__device__ float g_Up[Dn * NP];
__device__ float g_X[Tn * Bn * Dn];       // xs / h_seq in place, row = t*Bn+b
__device__ float g_XWraw[Tn * Bn * NP];
__device__ float g_spre[Tn * Bn * NP];
__device__ float g_Gpart[Bn * KS * NP];   // [b][ks][NP]
__device__ float g_h[Bn * Dn];
__device__ float g_fkseq[Tn * Bn];
__device__ float g_hvseq[Tn * Bn];
__device__ unsigned g_ctrM[NG * 64];      // monotonic counters, 256B apart
__device__ unsigned g_pCnt, g_pEp;        // global prep barrier

// --------------------------- f32x2 packed math ------------------------------
__device__ __forceinline__ void ffma2(u64t& d, u64t a, u64t b) {
    asm("fma.rn.f32x2 %0, %1, %2, %0;" : "+l"(d) : "l"(a), "l"(b));
}
__device__ __forceinline__ u64t packdup(float x) {
    u64t r; asm("mov.b64 %0, {%1, %1};" : "=l"(r) : "f"(x)); return r;
}
__device__ __forceinline__ float2 unpack2(u64t v) {
    float2 f; asm("mov.b64 {%0, %1}, %2;" : "=f"(f.x), "=f"(f.y) : "l"(v)); return f;
}

// ------------------------------ barriers ------------------------------------
__device__ __forceinline__ unsigned ld_acq(unsigned* p) {
    unsigned v;
    asm volatile("ld.acquire.gpu.u32 %0, [%1];" : "=r"(v) : "l"(p) : "memory");
    return v;
}
__device__ __forceinline__ void prep_barrier(unsigned& ep) {
    __syncthreads();
    if (threadIdx.x == 0) {
        ep += 1;
        __threadfence();
        unsigned prev = atomicAdd(&g_pCnt, 1u);
        if (prev == (unsigned)(NCTA - 1)) {
            atomicExch(&g_pCnt, 0u);
            __threadfence();
            atomicExch(&g_pEp, ep);
        } else {
            while (ld_acq(&g_pEp) < ep) { }
        }
        __threadfence();
    }
    __syncthreads();
}
__device__ __forceinline__ void bar_arrive(int g, unsigned& k) {
    __syncthreads();
    if (threadIdx.x == 0) {
        k += (unsigned)GCTA;
        __threadfence();
        asm volatile("red.release.gpu.add.u32 [%0], 1;" :: "l"(&g_ctrM[g * 64]) : "memory");
    }
}
__device__ __forceinline__ void bar_wait(int g, unsigned base, unsigned k) {
    if (threadIdx.x == 0) {
        while ((unsigned)(ld_acq(&g_ctrM[g * 64]) - base) < k) { }
        __threadfence();
    }
    __syncthreads();
}

// ------------------- staging helpers (256 threads) --------------------------
// A chunk: 32 rows x 64 k from A (lda), transposed into hT[k][row] (stride 36)
__device__ __forceinline__ void stage_AT(float* hT, const float* A, int lda, int k0) {
    int tid = threadIdx.x;
    int row = tid & 31;
    int kh  = (tid >> 5) << 3;     // 0..56 step 8
    const float* src = A + (size_t)row * lda + k0 + kh;
    float4 v0 = *(const float4*)src;
    float4 v1 = *(const float4*)(src + 4);
    hT[(kh + 0) * 36 + row] = v0.x;
    hT[(kh + 1) * 36 + row] = v0.y;
    hT[(kh + 2) * 36 + row] = v0.z;
    hT[(kh + 3) * 36 + row] = v0.w;
    hT[(kh + 4) * 36 + row] = v1.x;
    hT[(kh + 5) * 36 + row] = v1.y;
    hT[(kh + 6) * 36 + row] = v1.z;
    hT[(kh + 7) * 36 + row] = v1.w;
}
// B chunk: 64 k x 64 cols (row stride NP) -> Uc[k*64 + c]
__device__ __forceinline__ void stage_Bc(float* Uc, const float* Bg, int k0, int n0) {
    int tid = threadIdx.x;
    int kr = tid >> 2;
    int cq = (tid & 3) << 4;
    const float* src = Bg + (size_t)(k0 + kr) * NP + n0 + cq;
#pragma unroll
    for (int q = 0; q < 4; q++)
        *(float4*)&Uc[(kr << 6) + cq + (q << 2)] = *(const float4*)(src + (q << 2));
}
// 32x64 GEMM over one 64-K chunk; 256 threads, 2m x 4n microtile
__device__ __forceinline__ void gemm64(u64t acc[2][2], const float* hT,
                                       const float* Uc, int ty, int tx) {
#pragma unroll 16
    for (int kk = 0; kk < 64; kk++) {
        float2 a = *(const float2*)(hT + kk * 36 + (ty << 1));
        const u64t* up = (const u64t*)(Uc + (kk << 6) + (tx << 2));
        u64t b0 = up[0], b1 = up[1];
        u64t ad;
        ad = packdup(a.x); ffma2(acc[0][0], ad, b0); ffma2(acc[0][1], ad, b1);
        ad = packdup(a.y); ffma2(acc[1][0], ad, b0); ffma2(acc[1][1], ad, b1);
    }
}

// ------------------------------ main kernel ---------------------------------
__global__ void __launch_bounds__(NTHR, 2) hrnn_kernel(
    const float* __restrict__ x, const int* __restrict__ mask,
    const float* __restrict__ W, const float* __restrict__ U,
    const float* __restrict__ bias, const float* __restrict__ gam,
    const float* __restrict__ bet, float* __restrict__ out)
{
    __shared__ __align__(16) float sh_Uc[64 * 64];   // 16 KB
    __shared__ __align__(16) float sh_hT[64 * 36];   // 9.2 KB
    __shared__ float sh_s[Nn];
    __shared__ float sh_red[16];
    __shared__ float sh_sc[8];

    int cta = blockIdx.x, tid = threadIdx.x;
    int gtid = cta * NTHR + tid;
    const int nthr = NCTA * NTHR;

    // ------------------------------- prep -----------------------------------
    for (int i = gtid; i < Tn * Bn * Dn; i += nthr) {
        int d = i & (Dn - 1);
        int row = i >> 10;
        int t = row >> 7, b = row & 127;
        g_X[i] = (d < In) ? x[(b * Tn + t) * In + d] : 0.f;
    }
    for (int i = gtid; i < Dn * NP; i += nthr) {
        int col = i % NP, r = i / NP;
        float wv = 0.f, uv = 0.f;
        if (col < Nn) { wv = W[r * Nn + col]; uv = U[r * Nn + col]; }
        g_Wp[i] = wv;
        g_Up[i] = uv;
    }
    for (int i = gtid; i < Tn * Bn; i += nthr) { g_fkseq[i] = 0.f; g_hvseq[i] = 1.f; }

    int g = cta / GCTA;       // SM s hosts cta s and s+148 -> groups {0,2} or {1,3}
    int c = cta - g * GCTA;
    const int b0 = g * GB;

    unsigned base = 0, kbar = 0, epP = 0;
    if (tid == 0) {
        base = ld_acq(&g_ctrM[g * 64]);   // sample before any arrival this launch
        epP  = ld_acq(&g_pEp);
    }
    prep_barrier(epP);

    const float* gam0 = gam;
    const float* gam1 = gam + Nn;
    const float* bet0 = bet;
    const float* bet1 = bet + Nn;
    float g1a = gam1[tid], b1a = bet1[tid];
    float g1b = gam1[tid + 256], b1b = bet1[tid + 256];
    float g1z = gam1[512], b1z = bet1[512];
    float g1_0 = gam1[0], b1_0 = bet1[0];
    float bias0 = bias[0];

    int ks = c / 9, j = c - ks * 9;       // scan role (c < 72)
    int ty = tid >> 4, tx = tid & 15;     // gemm microtile role
    u64t acc[2][2];

    for (int lev = 0; lev < DEPTH; lev++) {
        // -------- xW GEMM: group's 1152 tiles of 32x64, K=1024 ---------------
        for (int tau = c; tau < Tn * 9; tau += GCTA) {
            int t = tau / 9, j2 = tau - t * 9;
            acc[0][0] = 0ull; acc[0][1] = 0ull; acc[1][0] = 0ull; acc[1][1] = 0ull;
            const float* Abase = &g_X[(size_t)(t * Bn + b0) * Dn];
            for (int ch = 0; ch < 16; ch++) {
                __syncthreads();
                stage_AT(sh_hT, Abase, Dn, ch * 64);
                stage_Bc(sh_Uc, g_Wp, ch * 64, j2 * 64);
                __syncthreads();
                gemm64(acc, sh_hT, sh_Uc, ty, tx);
            }
#pragma unroll
            for (int i = 0; i < 2; i++) {
                float2 p0 = unpack2(acc[i][0]), p1 = unpack2(acc[i][1]);
                *(float4*)&g_XWraw[(size_t)(t * Bn + b0 + (ty << 1) + i) * NP
                                   + j2 * 64 + (tx << 2)] =
                    make_float4(p0.x, p0.y, p1.x, p1.y);
            }
        }
        bar_arrive(g, kbar); bar_wait(g, base, kbar);

        // -------- LN of group's xW rows -> spre; zero group's h --------------
        for (int lr = c; lr < Tn * GB; lr += GCTA) {
            int t = lr >> 5, bl = lr & 31;
            const float* row = &g_XWraw[(size_t)(t * Bn + b0 + bl) * NP];
            float v0 = row[tid];
            float v1 = row[tid + 256];
            float v2 = (tid == 0) ? row[512] : 0.f;
            float s = v0 + v1 + v2;
            float q = v0 * v0 + v1 * v1 + v2 * v2;
#pragma unroll
            for (int o = 16; o > 0; o >>= 1) {
                s += __shfl_down_sync(0xffffffffu, s, o);
                q += __shfl_down_sync(0xffffffffu, q, o);
            }
            if ((tid & 31) == 0) { sh_red[tid >> 5] = s; sh_red[8 + (tid >> 5)] = q; }
            __syncthreads();
            if (tid == 0) {
                float S = 0.f, Q = 0.f;
#pragma unroll
                for (int w = 0; w < 8; w++) { S += sh_red[w]; Q += sh_red[8 + w]; }
                float mean = S * (1.f / (float)Nn);
                float var  = Q * (1.f / (float)Nn) - mean * mean;
                sh_sc[0] = mean;
                sh_sc[1] = 1.f / (sqrtf(var + EPSV) + EPSV);
            }
            __syncthreads();
            float mean = sh_sc[0], inv = sh_sc[1];
            float* o = &g_spre[(size_t)(t * Bn + b0 + bl) * NP];
            o[tid]       = gam0[tid] * ((v0 - mean) * inv) + bet0[tid] + bias[tid];
            o[tid + 256] = gam0[tid + 256] * ((v1 - mean) * inv) + bet0[tid + 256] + bias[tid + 256];
            if (tid == 0)
                o[512] = gam0[512] * ((v2 - mean) * inv) + bet0[512] + bias[512];
            __syncthreads();
        }
        for (int i = c * NTHR + tid; i < GB * Dn; i += GCTA * NTHR)
            g_h[(size_t)b0 * Dn + i] = 0.f;
        bar_arrive(g, kbar); bar_wait(g, base, kbar);

        // ------------------------------ scan ---------------------------------
        float fk_c = 0.f, hv_c = 0.f;
        int prevmk = 0;
        float spv0 = 0.f, spv1 = 0.f, spv2 = 0.f;
        float xt[4], ht[4];
        float fkpt = 0.f, fkpv = 0.f, hvpv = 0.f;
        int mval = 0;

        for (int t = 0; t < Tn; t++) {
            // ---- phase A: h@U partial tile 32x64, K=128 (2 chunks) ----------
            if (c < KS * 9) {
                acc[0][0] = 0ull; acc[0][1] = 0ull; acc[1][0] = 0ull; acc[1][1] = 0ull;
                for (int ch = 0; ch < 2; ch++) {
                    __syncthreads();
                    stage_AT(sh_hT, &g_h[(size_t)b0 * Dn], Dn, ks * 128 + ch * 64);
                    stage_Bc(sh_Uc, g_Up, ks * 128 + ch * 64, j * 64);
                    __syncthreads();
                    gemm64(acc, sh_hT, sh_Uc, ty, tx);
                }
#pragma unroll
                for (int i = 0; i < 2; i++) {
                    float2 p0 = unpack2(acc[i][0]), p1 = unpack2(acc[i][1]);
                    *(float4*)&g_Gpart[(size_t)((b0 + (ty << 1) + i) * KS + ks) * NP
                                       + j * 64 + (tx << 2)] =
                        make_float4(p0.x, p0.y, p1.x, p1.y);
                }
            }
            bar_arrive(g, kbar);
            // prefetch phase-B operands (all barrier-independent)
            if (c < GB) {
                int b = b0 + c;
                const float* sp = &g_spre[(size_t)(t * Bn + b) * NP];
                spv0 = sp[tid];
                spv1 = sp[tid + 256];
#pragma unroll
                for (int e = 0; e < 4; e++) {
                    xt[e] = g_X[(size_t)(t * Bn + b) * Dn + tid + (e << 8)];
                    ht[e] = g_h[(size_t)b * Dn + tid + (e << 8)];
                }
                if (tid == 0) {
                    spv2 = sp[512];
                    mval = mask[b * Tn + t];
                    fkpt = g_fkseq[t * Bn + b];
                    fkpv = (t + 1 < Tn) ? g_fkseq[(t + 1) * Bn + b] : 0.f;
                    hvpv = g_hvseq[t * Bn + b];
                }
            }
            bar_wait(g, base, kbar);

            // ---- phase B: one CTA per batch ---------------------------------
            if (c < GB) {
                int b = b0 + c;
                const float* gp = &g_Gpart[(size_t)b * KS * NP];
                float v0 = 0.f, v1 = 0.f, v2 = 0.f;
#pragma unroll
                for (int kq = 0; kq < KS; kq++) {
                    v0 += gp[kq * NP + tid];
                    v1 += gp[kq * NP + 256 + tid];
                    if (tid == 0) v2 += gp[kq * NP + 512];
                }
                float s = v0 + v1 + v2;
                float q = v0 * v0 + v1 * v1 + v2 * v2;
#pragma unroll
                for (int o = 16; o > 0; o >>= 1) {
                    s += __shfl_down_sync(0xffffffffu, s, o);
                    q += __shfl_down_sync(0xffffffffu, q, o);
                }
                if ((tid & 31) == 0) { sh_red[tid >> 5] = s; sh_red[8 + (tid >> 5)] = q; }
                __syncthreads();
                if (tid == 0) {
                    float S = 0.f, Q = 0.f;
#pragma unroll
                    for (int w = 0; w < 8; w++) { S += sh_red[w]; Q += sh_red[8 + w]; }
                    float mean = S * (1.f / (float)Nn);
                    float var  = Q * (1.f / (float)Nn) - mean * mean;
                    sh_sc[0] = mean;
                    sh_sc[1] = 1.f / (sqrtf(var + EPSV) + EPSV);
                }
                __syncthreads();
                float mean = sh_sc[0], inv = sh_sc[1];

                float s0 = spv0 + g1a * ((v0 - mean) * inv) + b1a;
                float s1 = spv1 + g1b * ((v1 - mean) * inv) + b1b;
                sh_s[tid]       = s0;
                sh_s[tid + 256] = s1;
                if (tid == 0)
                    sh_s[512] = spv2 + g1z * ((v2 - mean) * inv) + b1z;

                if (tid == 0) {
                    float sum2_0 = g1_0 * ((v0 - mean) * inv) + b1_0;
                    bool mk  = mval > 0;
                    bool mk2 = (t > 0) && (prevmk > 0) && !mk;

                    float fk_both = fminf(fmaxf(0.2f * s0 + 0.5f, 0.f), 1.f);
                    float fk_t1   = fminf(fmaxf(0.2f * (sum2_0 + bias0) + 0.5f, 0.f), 1.f);
                    float fk = fkpt + (1.f - fkpt) *
                               (fk_c * fk_both + (1.f - fk_c) * fk_t1);
                    if (mk2) fk = 0.f;

                    float h_only = hv_c * fk * (fkpv + (1.f - fkpv) * (1.f - hvpv));
                    float x_only = hvpv * (1.f - fkpv) * (1.f - fk + fk * (1.f - hv_c));
                    float both   = (1.f - fkpv) * fk * hv_c * hvpv;
                    float hv = 1.f - (1.f - h_only) * (1.f - x_only) * (1.f - both);

                    float fk_out = mk ? fk : fk_c;
                    float hv_out = mk ? hv : hv_c;
                    if (mk2) fk_out = 0.f;

                    sh_sc[2] = h_only; sh_sc[3] = x_only;
                    sh_sc[4] = both;   sh_sc[5] = mk ? 1.f : 0.f;

                    g_fkseq[t * Bn + b] = fk_out;
                    g_hvseq[t * Bn + b] = hv_out;
                    fk_c = fk_out; hv_c = hv_out; prevmk = mval;
                }
                __syncthreads();

                float h_only = sh_sc[2], x_only = sh_sc[3];
                float both = sh_sc[4], mkf = sh_sc[5];
#pragma unroll
                for (int e = 0; e < 4; e++) {
                    int d = tid + (e << 8);
                    float h_new = (d < In) ? 0.f : tanhf(sh_s[d - (In - 1)]);
                    float h = h_only * ht[e] + x_only * xt[e] + both * h_new;
                    h = mkf * h + (1.f - mkf) * ht[e];
                    g_h[(size_t)b * Dn + d] = h;
                    g_X[(size_t)(t * Bn + b) * Dn + d] = h;
                }
            }
            bar_arrive(g, kbar); bar_wait(g, base, kbar);
        }
    }

    // ------------------------------ output ----------------------------------
    for (int i = c * NTHR + tid; i < GB * Hn; i += GCTA * NTHR) {
        int bl = i >> 9, jj = i & 511;
        out[(size_t)(b0 + bl) * Hn + jj] = g_h[(size_t)(b0 + bl) * Dn + In + jj];
    }
}

// ------------------------------- launcher -----------------------------------
extern "C" void kernel_launch(void* const* d_in, const int* in_sizes, int n_in,
                              void* d_out, int out_size) {
    const float* x      = (const float*)d_in[0];
    const int*   mask   = (const int*)d_in[1];
    const float* W      = (const float*)d_in[2];
    const float* U      = (const float*)d_in[3];
    const float* bias   = (const float*)d_in[4];
    const float* gammas = (const float*)d_in[5];
    const float* betas  = (const float*)d_in[6];
    float* out = (float*)d_out;

    hrnn_kernel<<<NCTA, NTHR>>>(x, mask, W, U, bias, gammas, betas, out);
}

// round 17
// speedup vs baseline: 1.5820x; 1.5557x over previous
#include <cuda_runtime.h>
#include <math.h>

#define Bn    128
#define Tn    128
#define In    512
#define Hn    512
#define Dn    1024
#define Nn    513
#define NP    576
#define DEPTH 4
#define EPSV  1e-5f
#define NCTA  296          // 2 CTAs per SM
#define GCTA  148          // CTAs per group
#define GB    64           // batches per group
#define NTHR  256
#define KS    16           // split-K factor in scan

typedef unsigned long long u64t;

// ----------------------------- device state --------------------------------
__device__ float g_Wp[Dn * NP];
__device__ float g_Up[Dn * NP];
__device__ float g_X[Tn * Bn * Dn];        // xs / h_seq in place, row = t*Bn+b
__device__ float g_XWraw[Tn * Bn * NP];
__device__ float g_spre[Tn * Bn * NP];
__device__ float g_Gpart[2 * GB * KS * NP];  // [g][b][ks][NP] contiguous per batch
__device__ float g_h[Bn * Dn];
__device__ float g_fkseq[Tn * Bn];
__device__ float g_hvseq[Tn * Bn];
__device__ unsigned g_barCnt[4];           // 0,1: groups; 2: global
__device__ unsigned g_barEp[4];

// --------------------------- f32x2 packed math ------------------------------
__device__ __forceinline__ void ffma2(u64t& d, u64t a, u64t b) {
    asm("fma.rn.f32x2 %0, %1, %2, %0;" : "+l"(d) : "l"(a), "l"(b));
}
__device__ __forceinline__ u64t packdup(float x) {
    u64t r; asm("mov.b64 %0, {%1, %1};" : "=l"(r) : "f"(x)); return r;
}
__device__ __forceinline__ float2 unpack2(u64t v) {
    float2 f; asm("mov.b64 {%0, %1}, %2;" : "=f"(f.x), "=f"(f.y) : "l"(v)); return f;
}

// ------------------------------ barriers ------------------------------------
__device__ __forceinline__ unsigned ld_acq(unsigned* p) {
    unsigned v;
    asm volatile("ld.acquire.gpu.u32 %0, [%1];" : "=r"(v) : "l"(p) : "memory");
    return v;
}
__device__ __forceinline__ void barrier_sync(int idx, int n, unsigned& ep) {
    __syncthreads();
    if (threadIdx.x == 0) {
        ep += 1;
        __threadfence();
        unsigned prev = atomicAdd(&g_barCnt[idx], 1u);
        if (prev == (unsigned)(n - 1)) {
            atomicExch(&g_barCnt[idx], 0u);
            __threadfence();
            atomicExch(&g_barEp[idx], ep);
        } else {
            while (ld_acq(&g_barEp[idx]) < ep) { }
        }
        __threadfence();
    }
    __syncthreads();
}
__device__ __forceinline__ void bar_arrive(int idx, unsigned& ep) {
    __syncthreads();
    if (threadIdx.x == 0) {
        ep += 1;
        __threadfence();
        unsigned prev = atomicAdd(&g_barCnt[idx], 1u);
        if (prev == (unsigned)(GCTA - 1)) {
            atomicExch(&g_barCnt[idx], 0u);
            __threadfence();
            atomicExch(&g_barEp[idx], ep);
        }
    }
}
__device__ __forceinline__ void bar_wait(int idx, unsigned ep) {
    if (threadIdx.x == 0) {
        while (ld_acq(&g_barEp[idx]) < ep) { }
        __threadfence();
    }
    __syncthreads();
}

// --------------------- 64x64 tile GEMM (C stride = ldc) ---------------------
__device__ __forceinline__ void tile_gemm64(
    const float* __restrict__ A, int lda,
    const float* __restrict__ Bm,
    float* __restrict__ C, int K, float* sh, int ldc)
{
    float* hT = sh;            // [16][68]
    float* Us = sh + 16 * 68;  // [16][64]
    int tid  = threadIdx.x;
    int arow = tid >> 2, akq = (tid & 3) << 2;
    int brow = tid >> 4, bc  = (tid & 15) << 2;
    int ty   = tid >> 4, tx  = tid & 15;

    u64t acc2[4][2];
#pragma unroll
    for (int i = 0; i < 4; i++) { acc2[i][0] = 0ull; acc2[i][1] = 0ull; }

    const float* Aptr = A + arow * lda + akq;
    const float* Bptr = Bm + brow * NP + bc;
    float4 av = *(const float4*)Aptr;
    float4 bv = *(const float4*)Bptr;

    for (int k0 = 0; k0 < K; k0 += 16) {
        __syncthreads();
        hT[(akq + 0) * 68 + arow] = av.x;
        hT[(akq + 1) * 68 + arow] = av.y;
        hT[(akq + 2) * 68 + arow] = av.z;
        hT[(akq + 3) * 68 + arow] = av.w;
        *(float4*)(Us + (brow << 6) + bc) = bv;
        __syncthreads();
        if (k0 + 16 < K) {
            av = *(const float4*)(Aptr + k0 + 16);
            bv = *(const float4*)(Bptr + (size_t)(k0 + 16) * NP);
        }
#pragma unroll
        for (int kk = 0; kk < 16; kk++) {
            float4 a = *(float4*)(hT + kk * 68 + (ty << 2));
            const u64t* bp = (const u64t*)(Us + (kk << 6) + (tx << 2));
            u64t b0 = bp[0];
            u64t b1 = bp[1];
            u64t ad;
            ad = packdup(a.x); ffma2(acc2[0][0], ad, b0); ffma2(acc2[0][1], ad, b1);
            ad = packdup(a.y); ffma2(acc2[1][0], ad, b0); ffma2(acc2[1][1], ad, b1);
            ad = packdup(a.z); ffma2(acc2[2][0], ad, b0); ffma2(acc2[2][1], ad, b1);
            ad = packdup(a.w); ffma2(acc2[3][0], ad, b0); ffma2(acc2[3][1], ad, b1);
        }
    }
#pragma unroll
    for (int i = 0; i < 4; i++) {
        float2 lo = unpack2(acc2[i][0]);
        float2 hi = unpack2(acc2[i][1]);
        *(float4*)(C + (size_t)((ty << 2) + i) * ldc + (tx << 2)) =
            make_float4(lo.x, lo.y, hi.x, hi.y);
    }
}

// ------------------------------ main kernel ---------------------------------
__global__ void __launch_bounds__(NTHR, 2) hrnn_kernel(
    const float* __restrict__ x, const int* __restrict__ mask,
    const float* __restrict__ W, const float* __restrict__ U,
    const float* __restrict__ bias, const float* __restrict__ gam,
    const float* __restrict__ bet, float* __restrict__ out)
{
    __shared__ __align__(16) float sh_gemm[16 * 68 + 16 * 64];
    __shared__ float sh_s[Nn];
    __shared__ float sh_red[16];
    __shared__ float sh_sc[8];

    int cta = blockIdx.x, tid = threadIdx.x;
    int gtid = cta * NTHR + tid;
    const int nthr = NCTA * NTHR;

    // ------------------------------- prep -----------------------------------
    for (int i = gtid; i < Tn * Bn * Dn; i += nthr) {
        int d = i & (Dn - 1);
        int row = i >> 10;
        int t = row >> 7, b = row & 127;
        g_X[i] = (d < In) ? x[(b * Tn + t) * In + d] : 0.f;
    }
    for (int i = gtid; i < Dn * NP; i += nthr) {
        int col = i % NP, r = i / NP;
        float wv = 0.f, uv = 0.f;
        if (col < Nn) { wv = W[r * Nn + col]; uv = U[r * Nn + col]; }
        g_Wp[i] = wv;
        g_Up[i] = uv;
    }
    for (int i = gtid; i < Tn * Bn; i += nthr) { g_fkseq[i] = 0.f; g_hvseq[i] = 1.f; }

    // group interleave: each SM hosts one CTA of each group
    int g = cta & 1;
    int c = cta >> 1;
    unsigned epG = 0, epL = 0;
    if (tid == 0) {
        epG = ld_acq(&g_barEp[2]);
        epL = ld_acq(&g_barEp[g]);
    }
    barrier_sync(2, NCTA, epG);

    const float* gam0 = gam;
    const float* gam1 = gam + Nn;
    const float* bet0 = bet;
    const float* bet1 = bet + Nn;
    float g1a = gam1[tid], b1a = bet1[tid];
    float g1b = gam1[tid + 256], b1b = bet1[tid + 256];
    float g1z = gam1[512], b1z = bet1[512];
    float g1_0 = gam1[0], b1_0 = bet1[0];
    float bias0 = bias[0];
    const int b0g = g * GB;

    for (int lev = 0; lev < DEPTH; lev++) {
        // ---------------- xW GEMM: 128 t-tiles x 9 col strips ----------------
        for (int tau = c; tau < Tn * 9; tau += GCTA) {
            int t = tau / 9, j = tau - t * 9;
            tile_gemm64(&g_X[(size_t)(t * Bn + b0g) * Dn], Dn,
                        &g_Wp[j * 64],
                        &g_XWraw[(size_t)(t * Bn + b0g) * NP + j * 64],
                        Dn, sh_gemm, NP);
        }
        barrier_sync(g, GCTA, epL);

        // ---------------- LN of xW rows -> spre; zero h ----------------------
        for (int lr = c; lr < Tn * GB; lr += GCTA) {
            int t = lr >> 6, bl = lr & 63;
            const float* row = &g_XWraw[(size_t)(t * Bn + b0g + bl) * NP];
            float v0 = row[tid];
            float v1 = row[tid + 256];
            float v2 = (tid == 0) ? row[512] : 0.f;
            float s = v0 + v1 + v2;
            float q = v0 * v0 + v1 * v1 + v2 * v2;
#pragma unroll
            for (int o = 16; o > 0; o >>= 1) {
                s += __shfl_down_sync(0xffffffffu, s, o);
                q += __shfl_down_sync(0xffffffffu, q, o);
            }
            if ((tid & 31) == 0) { sh_red[tid >> 5] = s; sh_red[8 + (tid >> 5)] = q; }
            __syncthreads();
            if (tid == 0) {
                float S = 0.f, Q = 0.f;
#pragma unroll
                for (int w = 0; w < 8; w++) { S += sh_red[w]; Q += sh_red[8 + w]; }
                float mean = S * (1.f / (float)Nn);
                float var  = Q * (1.f / (float)Nn) - mean * mean;
                sh_sc[0] = mean;
                sh_sc[1] = 1.f / (sqrtf(var + EPSV) + EPSV);
            }
            __syncthreads();
            float mean = sh_sc[0], inv = sh_sc[1];
            float* o = &g_spre[(size_t)(t * Bn + b0g + bl) * NP];
            o[tid]       = gam0[tid] * ((v0 - mean) * inv) + bet0[tid] + bias[tid];
            o[tid + 256] = gam0[tid + 256] * ((v1 - mean) * inv) + bet0[tid + 256] + bias[tid + 256];
            if (tid == 0)
                o[512] = gam0[512] * ((v2 - mean) * inv) + bet0[512] + bias[512];
            __syncthreads();
        }
        for (int i = c * NTHR + tid; i < GB * Dn; i += GCTA * NTHR)
            g_h[(size_t)b0g * Dn + i] = 0.f;
        barrier_sync(g, GCTA, epL);

        // ------------------------------ scan ---------------------------------
        float fk_c = 0.f, hv_c = 0.f;      // register carries (c < GB)
        int prevmk = 0;
        float spv0 = 0.f, spv1 = 0.f, spv2 = 0.f;
        float xt[4], ht[4];
        float fkpt = 0.f, fkpv = 0.f, hvpv = 0.f;
        int mval = 0;

        for (int t = 0; t < Tn; t++) {
            // phase A: split-K h@U partials (144 of 148 CTAs, K-chunk = 64)
            if (c < 9 * KS) {
                int ks = c / 9, j = c - ks * 9;
                tile_gemm64(&g_h[(size_t)b0g * Dn + ks * 64], Dn,
                            &g_Up[(size_t)(ks * 64) * NP + j * 64],
                            &g_Gpart[(size_t)((g * GB) * KS + ks) * NP + j * 64],
                            64, sh_gemm, KS * NP);
            }
            bar_arrive(g, epL);
            // prefetch phase-B operands (barrier-independent)
            if (c < GB) {
                int b = b0g + c;
                const float* sp = &g_spre[(size_t)(t * Bn + b) * NP];
                spv0 = sp[tid];
                spv1 = sp[tid + 256];
#pragma unroll
                for (int e = 0; e < 4; e++) {
                    xt[e] = g_X[(size_t)(t * Bn + b) * Dn + tid + (e << 8)];
                    ht[e] = g_h[(size_t)b * Dn + tid + (e << 8)];
                }
                if (tid == 0) {
                    spv2 = sp[512];
                    mval = mask[b * Tn + t];
                    fkpt = g_fkseq[t * Bn + b];
                    fkpv = (t + 1 < Tn) ? g_fkseq[(t + 1) * Bn + b] : 0.f;
                    hvpv = g_hvseq[t * Bn + b];
                }
            }
            bar_wait(g, epL);

            // phase B: one CTA per batch
            if (c < GB) {
                int b = b0g + c;
                const float* gp = &g_Gpart[(size_t)((g * GB + c) * KS) * NP];
                float v0 = 0.f, v1 = 0.f, v2 = 0.f;
#pragma unroll
                for (int kq = 0; kq < KS; kq++) {
                    v0 += gp[kq * NP + tid];
                    v1 += gp[kq * NP + 256 + tid];
                    if (tid == 0) v2 += gp[kq * NP + 512];
                }
                float s = v0 + v1 + v2;
                float q = v0 * v0 + v1 * v1 + v2 * v2;
#pragma unroll
                for (int o = 16; o > 0; o >>= 1) {
                    s += __shfl_down_sync(0xffffffffu, s, o);
                    q += __shfl_down_sync(0xffffffffu, q, o);
                }
                if ((tid & 31) == 0) { sh_red[tid >> 5] = s; sh_red[8 + (tid >> 5)] = q; }
                __syncthreads();
                if (tid == 0) {
                    float S = 0.f, Q = 0.f;
#pragma unroll
                    for (int w = 0; w < 8; w++) { S += sh_red[w]; Q += sh_red[8 + w]; }
                    float mean = S * (1.f / (float)Nn);
                    float var  = Q * (1.f / (float)Nn) - mean * mean;
                    sh_sc[0] = mean;
                    sh_sc[1] = 1.f / (sqrtf(var + EPSV) + EPSV);
                }
                __syncthreads();
                float mean = sh_sc[0], inv = sh_sc[1];

                float s0 = spv0 + g1a * ((v0 - mean) * inv) + b1a;
                float s1 = spv1 + g1b * ((v1 - mean) * inv) + b1b;
                sh_s[tid]       = s0;
                sh_s[tid + 256] = s1;
                if (tid == 0)
                    sh_s[512] = spv2 + g1z * ((v2 - mean) * inv) + b1z;

                if (tid == 0) {
                    float sum2_0 = g1_0 * ((v0 - mean) * inv) + b1_0;
                    bool mk  = mval > 0;
                    bool mk2 = (t > 0) && (prevmk > 0) && !mk;

                    float fk_both = fminf(fmaxf(0.2f * s0 + 0.5f, 0.f), 1.f);
                    float fk_t1   = fminf(fmaxf(0.2f * (sum2_0 + bias0) + 0.5f, 0.f), 1.f);
                    float fk = fkpt + (1.f - fkpt) *
                               (fk_c * fk_both + (1.f - fk_c) * fk_t1);
                    if (mk2) fk = 0.f;

                    float h_only = hv_c * fk * (fkpv + (1.f - fkpv) * (1.f - hvpv));
                    float x_only = hvpv * (1.f - fkpv) * (1.f - fk + fk * (1.f - hv_c));
                    float both   = (1.f - fkpv) * fk * hv_c * hvpv;
                    float hv = 1.f - (1.f - h_only) * (1.f - x_only) * (1.f - both);

                    float fk_out = mk ? fk : fk_c;
                    float hv_out = mk ? hv : hv_c;
                    if (mk2) fk_out = 0.f;

                    sh_sc[2] = h_only; sh_sc[3] = x_only;
                    sh_sc[4] = both;   sh_sc[5] = mk ? 1.f : 0.f;

                    g_fkseq[t * Bn + b] = fk_out;
                    g_hvseq[t * Bn + b] = hv_out;
                    fk_c = fk_out; hv_c = hv_out; prevmk = mval;
                }
                __syncthreads();

                float h_only = sh_sc[2], x_only = sh_sc[3];
                float both = sh_sc[4], mkf = sh_sc[5];
#pragma unroll
                for (int e = 0; e < 4; e++) {
                    int d = tid + (e << 8);
                    float h_new = (d < In) ? 0.f : tanhf(sh_s[d - (In - 1)]);
                    float h = h_only * ht[e] + x_only * xt[e] + both * h_new;
                    h = mkf * h + (1.f - mkf) * ht[e];
                    g_h[(size_t)b * Dn + d] = h;
                    g_X[(size_t)(t * Bn + b) * Dn + d] = h;
                }
            }
            bar_arrive(g, epL);
            bar_wait(g, epL);
        }
    }

    // ------------------------------ output ----------------------------------
    for (int i = c * NTHR + tid; i < GB * Hn; i += GCTA * NTHR) {
        int bl = i >> 9, j = i & 511;
        out[(size_t)(b0g + bl) * Hn + j] = g_h[(size_t)(b0g + bl) * Dn + In + j];
    }
}

// ------------------------------- launcher -----------------------------------
extern "C" void kernel_launch(void* const* d_in, const int* in_sizes, int n_in,
                              void* d_out, int out_size) {
    const float* x      = (const float*)d_in[0];
    const int*   mask   = (const int*)d_in[1];
    const float* W      = (const float*)d_in[2];
    const float* U      = (const float*)d_in[3];
    const float* bias   = (const float*)d_in[4];
    const float* gammas = (const float*)d_in[5];
    const float* betas  = (const float*)d_in[6];
    float* out = (float*)d_out;

    hrnn_kernel<<<NCTA, NTHR>>>(x, mask, W, U, bias, gammas, betas, out);
}